// round 5
// baseline (speedup 1.0000x reference)
#include <cuda_runtime.h>
#include <cuda_bf16.h>
#include <math.h>

// 8192*8192 winner table, 64-bit entries:
//   packed = ((pair_idx+1) << 32) | float_bits(b[bucket]),  0 = untouched.
// atomicMax ordering is dominated by pair index (high word) -> last pair wins,
// and the winning entry already carries the output value in its low word.
// Zero-initialized at module load; each winner resets its cell during phase B,
// so every graph replay sees a zeroed table (deterministic).
#define N_CELLS (64u * 1024u * 1024u)
__device__ unsigned long long g_scratch[N_CELLS];

// Manual single-wave grid barrier (capture-safe, replay-deterministic):
// count self-resets, phase increases monotonically across uses/replays.
__device__ unsigned g_bar_count = 0;
__device__ unsigned g_bar_phase = 0;

__device__ __forceinline__ void grid_barrier() {
    __syncthreads();
    if (threadIdx.x == 0) {
        volatile unsigned* phase_v = &g_bar_phase;
        unsigned my_phase = *phase_v;
        __threadfence();                       // order elect writes before arrive
        unsigned arrived = atomicAdd(&g_bar_count, 1u);
        if (arrived == gridDim.x - 1) {
            g_bar_count = 0;                   // sole writer at this point
            __threadfence();
            atomicAdd(&g_bar_phase, 1u);       // release
        } else {
            while (*phase_v == my_phase) { }   // spin (1 thread/block)
        }
        __threadfence();                       // acquire
    }
    __syncthreads();
}

#define T_PER_BLK 512
#define N_BLKS    512          // 512 blocks x 512 thr = 262144 threads, single wave
#define PPT       2            // pairs per thread held in registers

// Fused elect + write. Phase A: atomicMax election into g_scratch.
// Phase B (after grid barrier): winners write b-value into out, reset scratch.
// Per-pair state survives in registers across the barrier -> no input reload;
// scratch sectors dirtied in A are L2-hot for B's reads.
__global__ void __launch_bounds__(T_PER_BLK, 4)
se_fused_kernel(const float* __restrict__ b,
                const int* __restrict__ src,
                const int* __restrict__ dst,
                const int* __restrict__ path_len,
                int n_pairs, int nn, int max_path,
                float* __restrict__ out_f) {
    const int tid = blockIdx.x * blockDim.x + threadIdx.x;
    const int nth = gridDim.x * blockDim.x;

    unsigned cell[PPT];
    unsigned long long packed[PPT];
    bool valid[PPT];

    // ---- Phase A: election ----
#pragma unroll
    for (int k = 0; k < PPT; k++) {
        int i = tid + k * nth;
        valid[k] = (i < n_pairs);
        if (valid[k]) {
            int pl = __ldg(&path_len[i]);
            int bu = (pl < max_path ? pl : max_path) - 1;
            if (bu < 0) bu = 0;
            unsigned fbits = __float_as_uint(__ldg(&b[bu]));
            packed[k] = ((unsigned long long)(unsigned)(i + 1) << 32) |
                        (unsigned long long)fbits;
            cell[k] = (unsigned)__ldg(&src[i]) * (unsigned)nn +
                      (unsigned)__ldg(&dst[i]);
        }
    }
#pragma unroll
    for (int k = 0; k < PPT; k++) {
        if (valid[k]) atomicMax(&g_scratch[cell[k]], packed[k]);
    }

    // tail (only if n_pairs > nth*PPT; not the case for this shape)
    for (int i = tid + PPT * nth; i < n_pairs; i += nth) {
        int pl = __ldg(&path_len[i]);
        int bu = (pl < max_path ? pl : max_path) - 1;
        if (bu < 0) bu = 0;
        unsigned long long p = ((unsigned long long)(unsigned)(i + 1) << 32) |
                               (unsigned long long)__float_as_uint(__ldg(&b[bu]));
        unsigned c = (unsigned)__ldg(&src[i]) * (unsigned)nn +
                     (unsigned)__ldg(&dst[i]);
        atomicMax(&g_scratch[c], p);
    }

    // ---- grid-wide barrier ----
    grid_barrier();

    // ---- Phase B: winners write, reset scratch ----
    unsigned long long w[PPT];
#pragma unroll
    for (int k = 0; k < PPT; k++) {
        if (valid[k]) w[k] = g_scratch[cell[k]];
    }
#pragma unroll
    for (int k = 0; k < PPT; k++) {
        if (valid[k] && w[k] == packed[k]) {
            out_f[cell[k]] = __uint_as_float((unsigned)packed[k]);
            g_scratch[cell[k]] = 0ull;   // self-clean for next replay
        }
    }
    for (int i = tid + PPT * nth; i < n_pairs; i += nth) {
        int pl = __ldg(&path_len[i]);
        int bu = (pl < max_path ? pl : max_path) - 1;
        if (bu < 0) bu = 0;
        unsigned long long p = ((unsigned long long)(unsigned)(i + 1) << 32) |
                               (unsigned long long)__float_as_uint(__ldg(&b[bu]));
        unsigned c = (unsigned)__ldg(&src[i]) * (unsigned)nn +
                     (unsigned)__ldg(&dst[i]);
        if (g_scratch[c] == p) {
            out_f[c] = __uint_as_float((unsigned)p);
            g_scratch[c] = 0ull;
        }
    }
}

extern "C" void kernel_launch(void* const* d_in, const int* in_sizes, int n_in,
                              void* d_out, int out_size) {
    // inputs: x [n_nodes,128] f32 (unused), b [max_path] f32,
    //         src [n_pairs] i32, dst [n_pairs] i32, path_len [n_pairs] i32
    const float* b        = (const float*)d_in[1];
    const int*   src      = (const int*)d_in[2];
    const int*   dst      = (const int*)d_in[3];
    const int*   path_len = (const int*)d_in[4];

    int max_path = in_sizes[1];
    int n_pairs  = in_sizes[2];
    int nn = (int)(sqrt((double)out_size) + 0.5);

    float* out_f = (float*)d_out;

    // 1) mandatory 256MB zero-fill at driver-memset bandwidth (best measured)
    cudaMemsetAsync(d_out, 0, (size_t)out_size * sizeof(float), 0);

    // 2) fused elect + write, single wave (512 blocks x 512 threads co-resident)
    se_fused_kernel<<<N_BLKS, T_PER_BLK>>>(b, src, dst, path_len,
                                           n_pairs, nn, max_path, out_f);
}